// round 3
// baseline (speedup 1.0000x reference)
#include <cuda_runtime.h>
#include <math_constants.h>

#define NPTS 8192
#define BATCH 4
#define KNNK 10

// ---------------- scratch arena (no allocation allowed) ----------------
#define O_X0     0u
#define O_IDX    196608u
#define O_X1     524288u
#define O_X2     2621440u
#define O_X3     4718592u
#define O_X4     6815744u
#define O_X5     13107200u
#define O_PMAX   46661632u
#define O_X5MAX  46792704u
#define O_BIAS   46796800u
#define O_Y1     46797824u
#define O_Y2     55186432u
#define O_Y3     63575040u
#define O_NORM   67769344u    // 4*8192 floats
#define SCRATCH_FLOATS 67802112u

__device__ __align__(16) float g_scratch[SCRATCH_FLOATS];

// ---------------- f32x2 packed helpers (sm_103a) ----------------
__device__ __forceinline__ unsigned long long pack2(float lo, float hi) {
    unsigned long long r;
    asm("mov.b64 %0, {%1, %2};" : "=l"(r) : "f"(lo), "f"(hi));
    return r;
}
__device__ __forceinline__ void unpack2(unsigned long long v, float& lo, float& hi) {
    asm("mov.b64 {%0, %1}, %2;" : "=f"(lo), "=f"(hi) : "l"(v));
}
__device__ __forceinline__ unsigned long long fma2(unsigned long long a,
                                                   unsigned long long b,
                                                   unsigned long long c) {
    unsigned long long d;
    asm("fma.rn.f32x2 %0, %1, %2, %3;" : "=l"(d) : "l"(a), "l"(b), "l"(c));
    return d;
}

// ---------------- build x0 = concat(targets, targets) ----------------
__global__ void build_x0_kernel(const float* __restrict__ t, float* __restrict__ x0) {
    int i = blockIdx.x * blockDim.x + threadIdx.x;
    if (i < BATCH * NPTS * 6) {
        int pt = i / 6, c = i % 6;
        x0[i] = t[pt * 3 + (c < 3 ? c : c - 3)];
    }
}

// ---------------- squared norms (C multiple of 4) ----------------
template<int C>
__global__ void norms_kernel(const float* __restrict__ x, float* __restrict__ norms) {
    int p = blockIdx.x * blockDim.x + threadIdx.x;
    if (p < BATCH * NPTS) {
        const float* row = x + (size_t)p * C;
        float s = 0.f;
        #pragma unroll
        for (int c = 0; c < C; c += 4) {
            float4 v = *(const float4*)(row + c);
            s = fmaf(v.x, v.x, s); s = fmaf(v.y, v.y, s);
            s = fmaf(v.z, v.z, s); s = fmaf(v.w, v.w, s);
        }
        norms[p] = s;
    }
}

// ---------------- KNN via tiled distance GEMM + fused top-k ----------------
// block 256, owns 128 queries; loops over 64 candidate tiles of 128.
// micro-tile 8 queries x 8 candidates per thread, packed f32x2 along queries.
template<int C>
__global__ __launch_bounds__(256, 2)
void knn_gemm_kernel(const float* __restrict__ x, const float* __restrict__ norms,
                     int* __restrict__ idxout) {
    extern __shared__ float smk[];
    float* As    = smk;                    // [C][128]
    float* Bs    = As + C * 128;           // [16][128]
    float* distS = Bs + 16 * 128;          // [128][129]
    float* tnS   = distS + 128 * 129;      // [128]

    const int b = blockIdx.y;
    const int q0 = blockIdx.x * 128;
    const float* xb = x + (size_t)b * NPTS * C;
    const float* nrm = norms + (size_t)b * NPTS;
    const int tid = threadIdx.x;
    const int tx = tid & 15, ty = tid >> 4;

    // preload full query tile, transposed: As[k][q]
    for (int idx = tid; idx < 128 * (C / 4); idx += 256) {
        int q = idx & 127, kq = idx >> 7;
        float4 v = *(const float4*)(xb + (size_t)(q0 + q) * C + kq * 4);
        As[(kq * 4 + 0) * 128 + q] = v.x;
        As[(kq * 4 + 1) * 128 + q] = v.y;
        As[(kq * 4 + 2) * 128 + q] = v.z;
        As[(kq * 4 + 3) * 128 + q] = v.w;
    }

    float bd[KNNK]; int bi[KNNK];
    #pragma unroll
    for (int i = 0; i < KNNK; i++) { bd[i] = CUDART_INF_F; bi[i] = 0; }

    for (int t0 = 0; t0 < NPTS; t0 += 128) {
        unsigned long long accp[4][8];
        #pragma unroll
        for (int rp = 0; rp < 4; rp++)
            #pragma unroll
            for (int c = 0; c < 8; c++) accp[rp][c] = 0ull;

        for (int kc = 0; kc < C; kc += 16) {
            __syncthreads();
            for (int idx = tid; idx < 128 * 4; idx += 256) {
                int j = idx & 127, kq = idx >> 7;
                float4 v = *(const float4*)(xb + (size_t)(t0 + j) * C + kc + kq * 4);
                Bs[(kq * 4 + 0) * 128 + j] = v.x;
                Bs[(kq * 4 + 1) * 128 + j] = v.y;
                Bs[(kq * 4 + 2) * 128 + j] = v.z;
                Bs[(kq * 4 + 3) * 128 + j] = v.w;
            }
            if (kc == 0 && tid < 128) tnS[tid] = nrm[t0 + tid];
            __syncthreads();
            #pragma unroll
            for (int kk = 0; kk < 16; kk++) {
                const float* arow = As + (kc + kk) * 128 + ty * 8;
                unsigned long long ap[4];
                #pragma unroll
                for (int rp = 0; rp < 4; rp++)
                    ap[rp] = *reinterpret_cast<const unsigned long long*>(arow + rp * 2);
                const float* brow = Bs + kk * 128 + tx * 8;
                float4 b0 = *(const float4*)(brow);
                float4 b1 = *(const float4*)(brow + 4);
                float bs8[8] = {b0.x, b0.y, b0.z, b0.w, b1.x, b1.y, b1.z, b1.w};
                #pragma unroll
                for (int c = 0; c < 8; c++) {
                    unsigned long long bdup = pack2(bs8[c], bs8[c]);
                    #pragma unroll
                    for (int rp = 0; rp < 4; rp++)
                        accp[rp][c] = fma2(ap[rp], bdup, accp[rp][c]);
                }
            }
        }
        __syncthreads();
        // write e = |x_j|^2 - 2*dot (query-norm constant: same ordering)
        #pragma unroll
        for (int c = 0; c < 8; c++) {
            int j = tx * 8 + c;
            float tn = tnS[j];
            #pragma unroll
            for (int rp = 0; rp < 4; rp++) {
                float lo, hi;
                unpack2(accp[rp][c], lo, hi);
                int q = ty * 8 + rp * 2;
                distS[q * 129 + j]       = fmaf(-2.f, lo, tn);
                distS[(q + 1) * 129 + j] = fmaf(-2.f, hi, tn);
            }
        }
        __syncthreads();
        if (tid < 128) {
            const float* drow = distS + tid * 129;
            #pragma unroll 4
            for (int j = 0; j < 128; j++) {
                float d = drow[j];
                if (d < bd[KNNK - 1]) {
                    bd[KNNK - 1] = d; bi[KNNK - 1] = t0 + j;
                    #pragma unroll
                    for (int s = KNNK - 1; s > 0; s--) {
                        if (bd[s] < bd[s - 1]) {
                            float td = bd[s]; bd[s] = bd[s - 1]; bd[s - 1] = td;
                            int   ti = bi[s]; bi[s] = bi[s - 1]; bi[s - 1] = ti;
                        }
                    }
                }
            }
        }
    }
    if (tid < 128) {
        int* o = idxout + ((size_t)b * NPTS + q0 + tid) * KNNK;
        #pragma unroll
        for (int i = 0; i < KNNK; i++) o[i] = bi[i];
    }
}

// ---------------- small-C KNN (C=6), thread per query ----------------
template<int C>
__global__ void knn_kernel(const float* __restrict__ x, int* __restrict__ idxout) {
    __shared__ float tile[128 * C];
    __shared__ float tnorm[128];
    const int b = blockIdx.y;
    const int q = blockIdx.x * 128 + threadIdx.x;
    const float* xb = x + (size_t)b * NPTS * C;

    float qf[C];
    float qn = 0.f;
    #pragma unroll
    for (int c = 0; c < C; c++) { qf[c] = xb[q * C + c]; qn = fmaf(qf[c], qf[c], qn); }

    float bd[KNNK]; int bi[KNNK];
    #pragma unroll
    for (int i = 0; i < KNNK; i++) { bd[i] = CUDART_INF_F; bi[i] = 0; }

    for (int t0 = 0; t0 < NPTS; t0 += 128) {
        __syncthreads();
        for (int i = threadIdx.x; i < 128 * C; i += 128) tile[i] = xb[t0 * C + i];
        __syncthreads();
        {
            float s = 0.f;
            #pragma unroll
            for (int c = 0; c < C; c++) {
                float v = tile[threadIdx.x * C + c];
                s = fmaf(v, v, s);
            }
            tnorm[threadIdx.x] = s;
        }
        __syncthreads();
        for (int j = 0; j < 128; j++) {
            float d0 = 0.f, d1 = 0.f;
            #pragma unroll
            for (int c = 0; c < C; c += 2) {
                d0 = fmaf(qf[c + 0], tile[j * C + c + 0], d0);
                d1 = fmaf(qf[c + 1], tile[j * C + c + 1], d1);
            }
            float d = qn + tnorm[j] - 2.f * (d0 + d1);
            if (d < bd[KNNK - 1]) {
                bd[KNNK - 1] = d; bi[KNNK - 1] = t0 + j;
                #pragma unroll
                for (int s = KNNK - 1; s > 0; s--) {
                    if (bd[s] < bd[s - 1]) {
                        float td = bd[s]; bd[s] = bd[s - 1]; bd[s - 1] = td;
                        int   ti = bi[s]; bi[s] = bi[s - 1]; bi[s - 1] = ti;
                    }
                }
            }
        }
    }
    int* o = idxout + ((size_t)b * NPTS + q) * KNNK;
    #pragma unroll
    for (int i = 0; i < KNNK; i++) o[i] = bi[i];
}

// ---------------- edge conv ----------------
template<int C, bool TWO>
__global__ void edge_conv_kernel(const float* __restrict__ x, const int* __restrict__ knn,
                                 const float* __restrict__ w1, const float* __restrict__ w2,
                                 const float* __restrict__ pa, int ai1, int ai2,
                                 float* __restrict__ out) {
    constexpr int F = 2 * C;
    constexpr int PPB = 16;
    extern __shared__ float sm[];
    float* ws1 = sm;
    float* ws2 = ws1 + F * 64;
    float* fb  = ws2 + (TWO ? 4096 : 0);
    float* h1b = fb + PPB * F;

    int tid = threadIdx.x;
    for (int i = tid; i < F * 64; i += 512) ws1[i] = w1[i];
    if (TWO) for (int i = tid; i < 4096; i += 512) ws2[i] = w2[i];
    float a1 = pa[ai1];
    float a2 = TWO ? pa[ai2] : 0.f;
    __syncthreads();

    int g = tid >> 5, lt = tid & 31;
    size_t pt = (size_t)blockIdx.x * PPB + g;
    int b = (int)(pt / NPTS);
    int n = (int)(pt % NPTS);
    const float* xb = x + (size_t)b * NPTS * C;
    const int* nbr = knn + pt * KNNK;
    float* f  = fb + g * F;
    float* h1 = h1b + g * 64;
    int ch = lt * 2;

    for (int c = lt; c < C; c += 32) f[C + c] = xb[n * C + c];

    float mx0 = -CUDART_INF_F, mx1 = -CUDART_INF_F;
    for (int j = 0; j < KNNK; j++) {
        int nb = nbr[j];
        __syncwarp();
        for (int c = lt; c < C; c += 32) f[c] = xb[nb * C + c] - f[C + c];
        __syncwarp();
        float s0 = 0.f, s1 = 0.f;
        #pragma unroll 8
        for (int c = 0; c < F; c++) {
            float fv = f[c];
            float2 wv = *(const float2*)(ws1 + c * 64 + ch);
            s0 = fmaf(fv, wv.x, s0);
            s1 = fmaf(fv, wv.y, s1);
        }
        float h0  = s0 >= 0.f ? s0 : a1 * s0;
        float hh1 = s1 >= 0.f ? s1 : a1 * s1;
        if (TWO) {
            h1[ch] = h0; h1[ch + 1] = hh1;
            __syncwarp();
            float t0 = 0.f, t1 = 0.f;
            #pragma unroll 8
            for (int c = 0; c < 64; c++) {
                float hv = h1[c];
                float2 wv = *(const float2*)(ws2 + c * 64 + ch);
                t0 = fmaf(hv, wv.x, t0);
                t1 = fmaf(hv, wv.y, t1);
            }
            h0  = t0 >= 0.f ? t0 : a2 * t0;
            hh1 = t1 >= 0.f ? t1 : a2 * t1;
        }
        mx0 = fmaxf(mx0, h0);
        mx1 = fmaxf(mx1, hh1);
    }
    out[pt * 64 + ch]     = mx0;
    out[pt * 64 + ch + 1] = mx1;
}

// ---------------- concat x4 = [x1|x2|x3] ----------------
__global__ void concat_x4_kernel(const float* __restrict__ x1, const float* __restrict__ x2,
                                 const float* __restrict__ x3, float* __restrict__ x4) {
    int i = blockIdx.x * 256 + threadIdx.x;
    if (i < BATCH * NPTS * 192) {
        int pt = i / 192, c = i % 192;
        float v = (c < 64) ? x1[pt * 64 + c]
                : (c < 128) ? x2[pt * 64 + c - 64]
                : x3[pt * 64 + c - 128];
        x4[i] = v;
    }
}

// ---------------- SGEMM (f32x2) + per-batch bias + PReLU ----------------
__global__ void gemm_prelu_kernel(const float* __restrict__ A, const float* __restrict__ B,
                                  float* __restrict__ C, const float* __restrict__ bias,
                                  const float* __restrict__ pa, int aidx,
                                  int K, int Nc) {
    __shared__ float As[16][64];
    __shared__ float Bs[16][64];
    int tid = threadIdx.x;
    int tx = tid & 15, ty = tid >> 4;
    int m0 = blockIdx.x * 64, n0 = blockIdx.y * 64;

    unsigned long long accp[4][4];
    #pragma unroll
    for (int rp = 0; rp < 4; rp++)
        #pragma unroll
        for (int c = 0; c < 4; c++) accp[rp][c] = 0ull;

    for (int k0 = 0; k0 < K; k0 += 16) {
        #pragma unroll
        for (int l = 0; l < 2; l++) {
            int i = tid * 2 + l;
            int m = i >> 2, kc = (i & 3) * 4;
            float4 v = *(const float4*)(A + (size_t)(m0 + m) * K + k0 + kc);
            As[kc + 0][m] = v.x; As[kc + 1][m] = v.y;
            As[kc + 2][m] = v.z; As[kc + 3][m] = v.w;
            int kb = i >> 4, nb = (i & 15) * 4;
            float4 w = *(const float4*)(B + (size_t)(k0 + kb) * Nc + n0 + nb);
            *(float4*)(&Bs[kb][nb]) = w;
        }
        __syncthreads();
        #pragma unroll
        for (int kk = 0; kk < 16; kk++) {
            unsigned long long ap[4];
            #pragma unroll
            for (int rp = 0; rp < 4; rp++)
                ap[rp] = *reinterpret_cast<const unsigned long long*>(&As[kk][ty * 8 + rp * 2]);
            float4 bv = *(const float4*)(&Bs[kk][tx * 4]);
            float bs4[4] = {bv.x, bv.y, bv.z, bv.w};
            #pragma unroll
            for (int c = 0; c < 4; c++) {
                unsigned long long bdup = pack2(bs4[c], bs4[c]);
                #pragma unroll
                for (int rp = 0; rp < 4; rp++)
                    accp[rp][c] = fma2(ap[rp], bdup, accp[rp][c]);
            }
        }
        __syncthreads();
    }

    float al = pa[aidx];
    #pragma unroll
    for (int rp = 0; rp < 4; rp++) {
        float lo[4], hi[4];
        #pragma unroll
        for (int c = 0; c < 4; c++) unpack2(accp[rp][c], lo[c], hi[c]);
        #pragma unroll
        for (int h = 0; h < 2; h++) {
            size_t m = (size_t)m0 + ty * 8 + rp * 2 + h;
            int n = n0 + tx * 4;
            float e0 = h ? hi[0] : lo[0], e1 = h ? hi[1] : lo[1];
            float e2 = h ? hi[2] : lo[2], e3 = h ? hi[3] : lo[3];
            if (bias) {
                const float* brow = bias + (m >> 13) * Nc;
                e0 += brow[n]; e1 += brow[n + 1]; e2 += brow[n + 2]; e3 += brow[n + 3];
            }
            float4 v;
            v.x = e0 >= 0.f ? e0 : al * e0;
            v.y = e1 >= 0.f ? e1 : al * e1;
            v.z = e2 >= 0.f ? e2 : al * e2;
            v.w = e3 >= 0.f ? e3 : al * e3;
            *(float4*)(C + m * Nc + n) = v;
        }
    }
}

// ---------------- global max over N + bias from w7 tail ----------------
__global__ void max1_kernel(const float* __restrict__ x5, float* __restrict__ pmax) {
    int b = blockIdx.y, chunk = blockIdx.x, c = threadIdx.x;
    const float* p = x5 + ((size_t)b * NPTS + (size_t)chunk * 256) * 1024 + c;
    float m = -CUDART_INF_F;
    for (int n = 0; n < 256; n++) m = fmaxf(m, p[(size_t)n * 1024]);
    pmax[((size_t)b * 32 + chunk) * 1024 + c] = m;
}
__global__ void max2_kernel(const float* __restrict__ pmax, float* __restrict__ x5max) {
    int b = blockIdx.x, c = threadIdx.x;
    float m = -CUDART_INF_F;
    for (int k = 0; k < 32; k++) m = fmaxf(m, pmax[((size_t)b * 32 + k) * 1024 + c]);
    x5max[b * 1024 + c] = m;
}
__global__ void bias_kernel(const float* __restrict__ x5max, const float* __restrict__ w7,
                            float* __restrict__ bias) {
    int b = blockIdx.x, j = threadIdx.x;
    float s = 0.f;
    for (int c = 0; c < 1024; c++)
        s = fmaf(x5max[b * 1024 + c], w7[(size_t)(192 + c) * 256 + j], s);
    bias[b * 256 + j] = s;
}

// ---------------- final 128->2 layer ----------------
__global__ void final_kernel(const float* __restrict__ y3, const float* __restrict__ w10,
                             const float* __restrict__ pa, float* __restrict__ out) {
    __shared__ float ws[256];
    int tid = threadIdx.x;
    ws[tid * 2] = w10[tid * 2];
    ws[tid * 2 + 1] = w10[tid * 2 + 1];
    __syncthreads();
    int warp = tid >> 5, lane = tid & 31;
    size_t pt = (size_t)blockIdx.x * 4 + warp;
    const float* row = y3 + pt * 128;
    float s0 = 0.f, s1 = 0.f;
    for (int c = lane; c < 128; c += 32) {
        float v = row[c];
        s0 = fmaf(v, ws[c * 2], s0);
        s1 = fmaf(v, ws[c * 2 + 1], s1);
    }
    #pragma unroll
    for (int o = 16; o > 0; o >>= 1) {
        s0 += __shfl_down_sync(0xffffffffu, s0, o);
        s1 += __shfl_down_sync(0xffffffffu, s1, o);
    }
    if (lane == 0) {
        float a = pa[9];
        out[pt * 2]     = s0 >= 0.f ? s0 : a * s0;
        out[pt * 2 + 1] = s1 >= 0.f ? s1 : a * s1;
    }
}

// ---------------- host orchestration ----------------
extern "C" void kernel_launch(void* const* d_in, const int* in_sizes, int n_in,
                              void* d_out, int out_size) {
    const float* targets = (const float*)d_in[0];
    const float* w[10];
    for (int i = 0; i < 10; i++) w[i] = (const float*)d_in[1 + i];
    const float* pa = (const float*)d_in[11];
    float* out = (float*)d_out;

    float* base = nullptr;
    cudaGetSymbolAddress((void**)&base, g_scratch);
    float* x0    = base + O_X0;
    int*   idx   = (int*)(base + O_IDX);
    float* x1    = base + O_X1;
    float* x2    = base + O_X2;
    float* x3    = base + O_X3;
    float* x4    = base + O_X4;
    float* x5    = base + O_X5;
    float* pmax  = base + O_PMAX;
    float* x5max = base + O_X5MAX;
    float* bias  = base + O_BIAS;
    float* y1    = base + O_Y1;
    float* y2    = base + O_Y2;
    float* y3    = base + O_Y3;
    float* nrm   = base + O_NORM;

    const int smem6t  = (12 * 64 + 4096 + 16 * 12 + 16 * 64) * 4;
    const int smem64t = (128 * 64 + 4096 + 16 * 128 + 16 * 64) * 4;
    const int smem64f = (128 * 64 + 16 * 128 + 16 * 64) * 4;
    const int smemKNN = (64 * 128 + 16 * 128 + 128 * 129 + 128) * 4;  // 107520

    cudaFuncSetAttribute(edge_conv_kernel<64, true>,
                         cudaFuncAttributeMaxDynamicSharedMemorySize, smem64t);
    cudaFuncSetAttribute(knn_gemm_kernel<64>,
                         cudaFuncAttributeMaxDynamicSharedMemorySize, smemKNN);

    build_x0_kernel<<<(BATCH * NPTS * 6 + 255) / 256, 256>>>(targets, x0);

    knn_kernel<6><<<dim3(NPTS / 128, BATCH), 128>>>(x0, idx);
    edge_conv_kernel<6, true><<<BATCH * NPTS / 16, 512, smem6t>>>(x0, idx, w[0], w[1], pa, 0, 1, x1);

    norms_kernel<64><<<(BATCH * NPTS + 255) / 256, 256>>>(x1, nrm);
    knn_gemm_kernel<64><<<dim3(NPTS / 128, BATCH), 256, smemKNN>>>(x1, nrm, idx);
    edge_conv_kernel<64, true><<<BATCH * NPTS / 16, 512, smem64t>>>(x1, idx, w[2], w[3], pa, 2, 3, x2);

    norms_kernel<64><<<(BATCH * NPTS + 255) / 256, 256>>>(x2, nrm);
    knn_gemm_kernel<64><<<dim3(NPTS / 128, BATCH), 256, smemKNN>>>(x2, nrm, idx);
    edge_conv_kernel<64, false><<<BATCH * NPTS / 16, 512, smem64f>>>(x2, idx, w[4], nullptr, pa, 4, 4, x3);

    concat_x4_kernel<<<(BATCH * NPTS * 192 + 255) / 256, 256>>>(x1, x2, x3, x4);

    gemm_prelu_kernel<<<dim3(BATCH * NPTS / 64, 1024 / 64), 128>>>(x4, w[5], x5, nullptr, pa, 5, 192, 1024);
    max1_kernel<<<dim3(32, BATCH), 1024>>>(x5, pmax);
    max2_kernel<<<BATCH, 1024>>>(pmax, x5max);
    bias_kernel<<<BATCH, 256>>>(x5max, w[6], bias);

    gemm_prelu_kernel<<<dim3(BATCH * NPTS / 64, 256 / 64), 128>>>(x4, w[6], y1, bias, pa, 6, 192, 256);
    gemm_prelu_kernel<<<dim3(BATCH * NPTS / 64, 256 / 64), 128>>>(y1, w[7], y2, nullptr, pa, 7, 256, 256);
    gemm_prelu_kernel<<<dim3(BATCH * NPTS / 64, 128 / 64), 128>>>(y2, w[8], y3, nullptr, pa, 8, 256, 128);
    final_kernel<<<BATCH * NPTS / 4, 128>>>(y3, w[9], pa, out);

    (void)in_sizes; (void)n_in; (void)out_size;
}

// round 4
// speedup vs baseline: 1.6898x; 1.6898x over previous
#include <cuda_runtime.h>
#include <math_constants.h>

#define NPTS 8192
#define BATCH 4
#define KNNK 10
#define NSPLIT 4
#define SPLITLEN (NPTS / NSPLIT)

// ---------------- scratch arena (no allocation allowed) ----------------
#define O_X0     0u
#define O_IDX    196608u
#define O_X1     524288u
#define O_X2     2621440u
#define O_X3     4718592u
#define O_X4     6815744u
#define O_X5     13107200u
#define O_PMAX   46661632u
#define O_X5MAX  46792704u
#define O_BIAS   46796800u
#define O_Y1     46797824u
#define O_Y2     55186432u
#define O_Y3     63575040u
#define O_SD     67769344u    // 4*8192*4*10 = 1310720 floats
#define O_SI     69080064u    // 1310720 ints
#define SCRATCH_FLOATS 70390784u

__device__ __align__(16) float g_scratch[SCRATCH_FLOATS];

// ---------------- f32x2 packed helpers (sm_103a) ----------------
__device__ __forceinline__ void unpack2(unsigned long long v, float& lo, float& hi) {
    asm("mov.b64 {%0, %1}, %2;" : "=f"(lo), "=f"(hi) : "l"(v));
}
__device__ __forceinline__ unsigned long long fma2(unsigned long long a,
                                                   unsigned long long b,
                                                   unsigned long long c) {
    unsigned long long d;
    asm("fma.rn.f32x2 %0, %1, %2, %3;" : "=l"(d) : "l"(a), "l"(b), "l"(c));
    return d;
}

// ---------------- build x0 = concat(targets, targets) ----------------
__global__ void build_x0_kernel(const float* __restrict__ t, float* __restrict__ x0) {
    int i = blockIdx.x * blockDim.x + threadIdx.x;
    if (i < BATCH * NPTS * 6) {
        int pt = i / 6, c = i % 6;
        x0[i] = t[pt * 3 + (c < 3 ? c : c - 3)];
    }
}

// ---------------- small-C KNN (C=6), thread per query (R2-proven) ----------------
template<int C>
__global__ void knn_kernel(const float* __restrict__ x, int* __restrict__ idxout) {
    __shared__ float tile[128 * C];
    __shared__ float tnorm[128];
    const int b = blockIdx.y;
    const int q = blockIdx.x * 128 + threadIdx.x;
    const float* xb = x + (size_t)b * NPTS * C;

    float qf[C];
    float qn = 0.f;
    #pragma unroll
    for (int c = 0; c < C; c++) { qf[c] = xb[q * C + c]; qn = fmaf(qf[c], qf[c], qn); }

    float bd[KNNK]; int bi[KNNK];
    #pragma unroll
    for (int i = 0; i < KNNK; i++) { bd[i] = CUDART_INF_F; bi[i] = 0; }

    for (int t0 = 0; t0 < NPTS; t0 += 128) {
        __syncthreads();
        for (int i = threadIdx.x; i < 128 * C; i += 128) tile[i] = xb[t0 * C + i];
        __syncthreads();
        {
            float s = 0.f;
            #pragma unroll
            for (int c = 0; c < C; c++) {
                float v = tile[threadIdx.x * C + c];
                s = fmaf(v, v, s);
            }
            tnorm[threadIdx.x] = s;
        }
        __syncthreads();
        for (int j = 0; j < 128; j++) {
            float d0 = 0.f, d1 = 0.f;
            #pragma unroll
            for (int c = 0; c < C; c += 2) {
                d0 = fmaf(qf[c + 0], tile[j * C + c + 0], d0);
                d1 = fmaf(qf[c + 1], tile[j * C + c + 1], d1);
            }
            float d = qn + tnorm[j] - 2.f * (d0 + d1);
            if (d < bd[KNNK - 1]) {
                bd[KNNK - 1] = d; bi[KNNK - 1] = t0 + j;
                #pragma unroll
                for (int s = KNNK - 1; s > 0; s--) {
                    if (bd[s] < bd[s - 1]) {
                        float td = bd[s]; bd[s] = bd[s - 1]; bd[s - 1] = td;
                        int   ti = bi[s]; bi[s] = bi[s - 1]; bi[s - 1] = ti;
                    }
                }
            }
        }
    }
    int* o = idxout + ((size_t)b * NPTS + q) * KNNK;
    #pragma unroll
    for (int i = 0; i < KNNK; i++) o[i] = bi[i];
}

// ---------------- KNN C=64: candidate-split + packed f32x2 dot ----------------
// grid (NPTS/128, NSPLIT, BATCH), block 128, thread per query.
// e = |x_j|^2 - 2*dot (query norm dropped: per-query-constant, ordering exact).
template<int C>
__global__ __launch_bounds__(128)
void knn_split_kernel(const float* __restrict__ x,
                      float* __restrict__ sd, int* __restrict__ si) {
    __shared__ float tile[128 * C];
    __shared__ float tnorm[128];
    const int b = blockIdx.z;
    const int sp = blockIdx.y;
    const int q = blockIdx.x * 128 + threadIdx.x;
    const float* xb = x + (size_t)b * NPTS * C;
    const int cand0 = sp * SPLITLEN;

    // query row packed as f32x2 pairs
    unsigned long long qp[C / 2];
    {
        const ulonglong2* qr = (const ulonglong2*)(xb + (size_t)q * C);
        #pragma unroll
        for (int i = 0; i < C / 4; i++) {
            ulonglong2 v = qr[i];
            qp[2 * i] = v.x; qp[2 * i + 1] = v.y;
        }
    }

    float bd[KNNK]; int bi[KNNK];
    #pragma unroll
    for (int i = 0; i < KNNK; i++) { bd[i] = CUDART_INF_F; bi[i] = 0; }

    for (int t0 = cand0; t0 < cand0 + SPLITLEN; t0 += 128) {
        __syncthreads();
        {
            const float4* src = (const float4*)(xb + (size_t)t0 * C);
            float4* dst = (float4*)tile;
            for (int i = threadIdx.x; i < 128 * (C / 4); i += 128) dst[i] = src[i];
        }
        __syncthreads();
        {
            const unsigned long long* tr =
                (const unsigned long long*)(tile + threadIdx.x * C);
            unsigned long long a0 = 0ull, a1 = 0ull;
            #pragma unroll
            for (int i = 0; i < C / 2; i += 2) {
                a0 = fma2(tr[i], tr[i], a0);
                a1 = fma2(tr[i + 1], tr[i + 1], a1);
            }
            float l0, h0, l1, h1;
            unpack2(a0, l0, h0); unpack2(a1, l1, h1);
            tnorm[threadIdx.x] = (l0 + h0) + (l1 + h1);
        }
        __syncthreads();
        for (int j = 0; j < 128; j++) {
            const unsigned long long* tr = (const unsigned long long*)(tile + j * C);
            unsigned long long a0 = 0ull, a1 = 0ull, a2 = 0ull, a3 = 0ull;
            #pragma unroll
            for (int i = 0; i < C / 2; i += 4) {
                a0 = fma2(qp[i + 0], tr[i + 0], a0);
                a1 = fma2(qp[i + 1], tr[i + 1], a1);
                a2 = fma2(qp[i + 2], tr[i + 2], a2);
                a3 = fma2(qp[i + 3], tr[i + 3], a3);
            }
            float l0, h0, l1, h1, l2, h2, l3, h3;
            unpack2(a0, l0, h0); unpack2(a1, l1, h1);
            unpack2(a2, l2, h2); unpack2(a3, l3, h3);
            float dot = ((l0 + h0) + (l1 + h1)) + ((l2 + h2) + (l3 + h3));
            float d = fmaf(-2.f, dot, tnorm[j]);
            if (d < bd[KNNK - 1]) {
                bd[KNNK - 1] = d; bi[KNNK - 1] = t0 + j;
                #pragma unroll
                for (int s = KNNK - 1; s > 0; s--) {
                    if (bd[s] < bd[s - 1]) {
                        float td = bd[s]; bd[s] = bd[s - 1]; bd[s - 1] = td;
                        int   ti = bi[s]; bi[s] = bi[s - 1]; bi[s - 1] = ti;
                    }
                }
            }
        }
    }
    size_t o = (((size_t)b * NPTS + q) * NSPLIT + sp) * KNNK;
    #pragma unroll
    for (int i = 0; i < KNNK; i++) { sd[o + i] = bd[i]; si[o + i] = bi[i]; }
}

// merge NSPLIT partial top-10 lists into final indices
__global__ void knn_merge_kernel(const float* __restrict__ sd, const int* __restrict__ si,
                                 int* __restrict__ idxout) {
    int p = blockIdx.x * 256 + threadIdx.x;
    if (p >= BATCH * NPTS) return;
    const float* d = sd + (size_t)p * NSPLIT * KNNK;
    const int* ix = si + (size_t)p * NSPLIT * KNNK;
    float bd[KNNK]; int bi[KNNK];
    #pragma unroll
    for (int i = 0; i < KNNK; i++) { bd[i] = CUDART_INF_F; bi[i] = 0; }
    #pragma unroll 4
    for (int s = 0; s < NSPLIT * KNNK; s++) {
        float dv = d[s];
        if (dv < bd[KNNK - 1]) {
            bd[KNNK - 1] = dv; bi[KNNK - 1] = ix[s];
            #pragma unroll
            for (int t = KNNK - 1; t > 0; t--) {
                if (bd[t] < bd[t - 1]) {
                    float td = bd[t]; bd[t] = bd[t - 1]; bd[t - 1] = td;
                    int   ti = bi[t]; bi[t] = bi[t - 1]; bi[t - 1] = ti;
                }
            }
        }
    }
    int* o = idxout + (size_t)p * KNNK;
    #pragma unroll
    for (int i = 0; i < KNNK; i++) o[i] = bi[i];
}

// ---------------- edge conv (R2-proven) ----------------
template<int C, bool TWO>
__global__ void edge_conv_kernel(const float* __restrict__ x, const int* __restrict__ knn,
                                 const float* __restrict__ w1, const float* __restrict__ w2,
                                 const float* __restrict__ pa, int ai1, int ai2,
                                 float* __restrict__ out) {
    constexpr int F = 2 * C;
    constexpr int PPB = 16;
    extern __shared__ float sm[];
    float* ws1 = sm;
    float* ws2 = ws1 + F * 64;
    float* fb  = ws2 + (TWO ? 4096 : 0);
    float* h1b = fb + PPB * F;

    int tid = threadIdx.x;
    for (int i = tid; i < F * 64; i += 512) ws1[i] = w1[i];
    if (TWO) for (int i = tid; i < 4096; i += 512) ws2[i] = w2[i];
    float a1 = pa[ai1];
    float a2 = TWO ? pa[ai2] : 0.f;
    __syncthreads();

    int g = tid >> 5, lt = tid & 31;
    size_t pt = (size_t)blockIdx.x * PPB + g;
    int b = (int)(pt / NPTS);
    int n = (int)(pt % NPTS);
    const float* xb = x + (size_t)b * NPTS * C;
    const int* nbr = knn + pt * KNNK;
    float* f  = fb + g * F;
    float* h1 = h1b + g * 64;
    int ch = lt * 2;

    for (int c = lt; c < C; c += 32) f[C + c] = xb[n * C + c];

    float mx0 = -CUDART_INF_F, mx1 = -CUDART_INF_F;
    for (int j = 0; j < KNNK; j++) {
        int nb = nbr[j];
        __syncwarp();
        for (int c = lt; c < C; c += 32) f[c] = xb[nb * C + c] - f[C + c];
        __syncwarp();
        float s0 = 0.f, s1 = 0.f;
        #pragma unroll 8
        for (int c = 0; c < F; c++) {
            float fv = f[c];
            float2 wv = *(const float2*)(ws1 + c * 64 + ch);
            s0 = fmaf(fv, wv.x, s0);
            s1 = fmaf(fv, wv.y, s1);
        }
        float h0  = s0 >= 0.f ? s0 : a1 * s0;
        float hh1 = s1 >= 0.f ? s1 : a1 * s1;
        if (TWO) {
            h1[ch] = h0; h1[ch + 1] = hh1;
            __syncwarp();
            float t0 = 0.f, t1 = 0.f;
            #pragma unroll 8
            for (int c = 0; c < 64; c++) {
                float hv = h1[c];
                float2 wv = *(const float2*)(ws2 + c * 64 + ch);
                t0 = fmaf(hv, wv.x, t0);
                t1 = fmaf(hv, wv.y, t1);
            }
            h0  = t0 >= 0.f ? t0 : a2 * t0;
            hh1 = t1 >= 0.f ? t1 : a2 * t1;
        }
        mx0 = fmaxf(mx0, h0);
        mx1 = fmaxf(mx1, hh1);
    }
    out[pt * 64 + ch]     = mx0;
    out[pt * 64 + ch + 1] = mx1;
}

// ---------------- concat x4 = [x1|x2|x3] ----------------
__global__ void concat_x4_kernel(const float* __restrict__ x1, const float* __restrict__ x2,
                                 const float* __restrict__ x3, float* __restrict__ x4) {
    int i = blockIdx.x * 256 + threadIdx.x;
    if (i < BATCH * NPTS * 192) {
        int pt = i / 192, c = i % 192;
        float v = (c < 64) ? x1[pt * 64 + c]
                : (c < 128) ? x2[pt * 64 + c - 64]
                : x3[pt * 64 + c - 128];
        x4[i] = v;
    }
}

// ---------------- SGEMM + per-batch bias + PReLU epilogue (R2-proven) ----------------
__global__ void gemm_prelu_kernel(const float* __restrict__ A, const float* __restrict__ B,
                                  float* __restrict__ C, const float* __restrict__ bias,
                                  const float* __restrict__ pa, int aidx,
                                  int K, int Nc) {
    __shared__ float As[16][64];
    __shared__ float Bs[16][64];
    int tid = threadIdx.x;
    int tx = tid & 15, ty = tid >> 4;
    int m0 = blockIdx.x * 64, n0 = blockIdx.y * 64;

    float acc[8][4];
    #pragma unroll
    for (int r = 0; r < 8; r++)
        #pragma unroll
        for (int c = 0; c < 4; c++) acc[r][c] = 0.f;

    for (int k0 = 0; k0 < K; k0 += 16) {
        #pragma unroll
        for (int l = 0; l < 2; l++) {
            int i = tid * 2 + l;
            int m = i >> 2, kc = (i & 3) * 4;
            float4 v = *(const float4*)(A + (size_t)(m0 + m) * K + k0 + kc);
            As[kc + 0][m] = v.x; As[kc + 1][m] = v.y;
            As[kc + 2][m] = v.z; As[kc + 3][m] = v.w;
            int kb = i >> 4, nb = (i & 15) * 4;
            float4 w = *(const float4*)(B + (size_t)(k0 + kb) * Nc + n0 + nb);
            *(float4*)(&Bs[kb][nb]) = w;
        }
        __syncthreads();
        #pragma unroll
        for (int kk = 0; kk < 16; kk++) {
            float a[8], bb[4];
            #pragma unroll
            for (int r = 0; r < 8; r++) a[r] = As[kk][ty * 8 + r];
            #pragma unroll
            for (int c = 0; c < 4; c++) bb[c] = Bs[kk][tx * 4 + c];
            #pragma unroll
            for (int r = 0; r < 8; r++)
                #pragma unroll
                for (int c = 0; c < 4; c++)
                    acc[r][c] = fmaf(a[r], bb[c], acc[r][c]);
        }
        __syncthreads();
    }

    float al = pa[aidx];
    #pragma unroll
    for (int r = 0; r < 8; r++) {
        size_t m = (size_t)m0 + ty * 8 + r;
        int n = n0 + tx * 4;
        float4 v;
        float bv0 = 0.f, bv1 = 0.f, bv2 = 0.f, bv3 = 0.f;
        if (bias) {
            const float* brow = bias + (m >> 13) * Nc;
            bv0 = brow[n]; bv1 = brow[n + 1]; bv2 = brow[n + 2]; bv3 = brow[n + 3];
        }
        float e0 = acc[r][0] + bv0, e1 = acc[r][1] + bv1;
        float e2 = acc[r][2] + bv2, e3 = acc[r][3] + bv3;
        v.x = e0 >= 0.f ? e0 : al * e0;
        v.y = e1 >= 0.f ? e1 : al * e1;
        v.z = e2 >= 0.f ? e2 : al * e2;
        v.w = e3 >= 0.f ? e3 : al * e3;
        *(float4*)(C + m * Nc + n) = v;
    }
}

// ---------------- global max over N + bias from w7 tail ----------------
__global__ void max1_kernel(const float* __restrict__ x5, float* __restrict__ pmax) {
    int b = blockIdx.y, chunk = blockIdx.x, c = threadIdx.x;
    const float* p = x5 + ((size_t)b * NPTS + (size_t)chunk * 256) * 1024 + c;
    float m = -CUDART_INF_F;
    for (int n = 0; n < 256; n++) m = fmaxf(m, p[(size_t)n * 1024]);
    pmax[((size_t)b * 32 + chunk) * 1024 + c] = m;
}
__global__ void max2_kernel(const float* __restrict__ pmax, float* __restrict__ x5max) {
    int b = blockIdx.x, c = threadIdx.x;
    float m = -CUDART_INF_F;
    for (int k = 0; k < 32; k++) m = fmaxf(m, pmax[((size_t)b * 32 + k) * 1024 + c]);
    x5max[b * 1024 + c] = m;
}
__global__ void bias_kernel(const float* __restrict__ x5max, const float* __restrict__ w7,
                            float* __restrict__ bias) {
    int b = blockIdx.x, j = threadIdx.x;
    float s = 0.f;
    for (int c = 0; c < 1024; c++)
        s = fmaf(x5max[b * 1024 + c], w7[(size_t)(192 + c) * 256 + j], s);
    bias[b * 256 + j] = s;
}

// ---------------- final 128->2 layer ----------------
__global__ void final_kernel(const float* __restrict__ y3, const float* __restrict__ w10,
                             const float* __restrict__ pa, float* __restrict__ out) {
    __shared__ float ws[256];
    int tid = threadIdx.x;
    ws[tid * 2] = w10[tid * 2];
    ws[tid * 2 + 1] = w10[tid * 2 + 1];
    __syncthreads();
    int warp = tid >> 5, lane = tid & 31;
    size_t pt = (size_t)blockIdx.x * 4 + warp;
    const float* row = y3 + pt * 128;
    float s0 = 0.f, s1 = 0.f;
    for (int c = lane; c < 128; c += 32) {
        float v = row[c];
        s0 = fmaf(v, ws[c * 2], s0);
        s1 = fmaf(v, ws[c * 2 + 1], s1);
    }
    #pragma unroll
    for (int o = 16; o > 0; o >>= 1) {
        s0 += __shfl_down_sync(0xffffffffu, s0, o);
        s1 += __shfl_down_sync(0xffffffffu, s1, o);
    }
    if (lane == 0) {
        float a = pa[9];
        out[pt * 2]     = s0 >= 0.f ? s0 : a * s0;
        out[pt * 2 + 1] = s1 >= 0.f ? s1 : a * s1;
    }
}

// ---------------- host orchestration ----------------
extern "C" void kernel_launch(void* const* d_in, const int* in_sizes, int n_in,
                              void* d_out, int out_size) {
    const float* targets = (const float*)d_in[0];
    const float* w[10];
    for (int i = 0; i < 10; i++) w[i] = (const float*)d_in[1 + i];
    const float* pa = (const float*)d_in[11];
    float* out = (float*)d_out;

    float* base = nullptr;
    cudaGetSymbolAddress((void**)&base, g_scratch);
    float* x0    = base + O_X0;
    int*   idx   = (int*)(base + O_IDX);
    float* x1    = base + O_X1;
    float* x2    = base + O_X2;
    float* x3    = base + O_X3;
    float* x4    = base + O_X4;
    float* x5    = base + O_X5;
    float* pmax  = base + O_PMAX;
    float* x5max = base + O_X5MAX;
    float* bias  = base + O_BIAS;
    float* y1    = base + O_Y1;
    float* y2    = base + O_Y2;
    float* y3    = base + O_Y3;
    float* sd    = base + O_SD;
    int*   si    = (int*)(base + O_SI);

    const int smem6t  = (12 * 64 + 4096 + 16 * 12 + 16 * 64) * 4;
    const int smem64t = (128 * 64 + 4096 + 16 * 128 + 16 * 64) * 4;
    const int smem64f = (128 * 64 + 16 * 128 + 16 * 64) * 4;

    cudaFuncSetAttribute(edge_conv_kernel<64, true>,
                         cudaFuncAttributeMaxDynamicSharedMemorySize, smem64t);

    build_x0_kernel<<<(BATCH * NPTS * 6 + 255) / 256, 256>>>(targets, x0);

    knn_kernel<6><<<dim3(NPTS / 128, BATCH), 128>>>(x0, idx);
    edge_conv_kernel<6, true><<<BATCH * NPTS / 16, 512, smem6t>>>(x0, idx, w[0], w[1], pa, 0, 1, x1);

    knn_split_kernel<64><<<dim3(NPTS / 128, NSPLIT, BATCH), 128>>>(x1, sd, si);
    knn_merge_kernel<<<(BATCH * NPTS + 255) / 256, 256>>>(sd, si, idx);
    edge_conv_kernel<64, true><<<BATCH * NPTS / 16, 512, smem64t>>>(x1, idx, w[2], w[3], pa, 2, 3, x2);

    knn_split_kernel<64><<<dim3(NPTS / 128, NSPLIT, BATCH), 128>>>(x2, sd, si);
    knn_merge_kernel<<<(BATCH * NPTS + 255) / 256, 256>>>(sd, si, idx);
    edge_conv_kernel<64, false><<<BATCH * NPTS / 16, 512, smem64f>>>(x2, idx, w[4], nullptr, pa, 4, 4, x3);

    concat_x4_kernel<<<(BATCH * NPTS * 192 + 255) / 256, 256>>>(x1, x2, x3, x4);

    gemm_prelu_kernel<<<dim3(BATCH * NPTS / 64, 1024 / 64), 128>>>(x4, w[5], x5, nullptr, pa, 5, 192, 1024);
    max1_kernel<<<dim3(32, BATCH), 1024>>>(x5, pmax);
    max2_kernel<<<BATCH, 1024>>>(pmax, x5max);
    bias_kernel<<<BATCH, 256>>>(x5max, w[6], bias);

    gemm_prelu_kernel<<<dim3(BATCH * NPTS / 64, 256 / 64), 128>>>(x4, w[6], y1, bias, pa, 6, 192, 256);
    gemm_prelu_kernel<<<dim3(BATCH * NPTS / 64, 256 / 64), 128>>>(y1, w[7], y2, nullptr, pa, 7, 256, 256);
    gemm_prelu_kernel<<<dim3(BATCH * NPTS / 64, 128 / 64), 128>>>(y2, w[8], y3, nullptr, pa, 8, 256, 128);
    final_kernel<<<BATCH * NPTS / 4, 128>>>(y3, w[9], pa, out);

    (void)in_sizes; (void)n_in; (void)out_size;
}

// round 5
// speedup vs baseline: 1.7518x; 1.0367x over previous
#include <cuda_runtime.h>
#include <math_constants.h>

#define NPTS 8192
#define BATCH 4
#define KNNK 10
#define NSPLIT 4
#define SPLITLEN (NPTS / NSPLIT)

// ---------------- scratch arena (no allocation allowed) ----------------
#define O_X0     0u
#define O_IDX    196608u
#define O_X1     524288u
#define O_X2     2621440u
#define O_X3     4718592u
#define O_X4     6815744u
#define O_X5     13107200u
#define O_PMAX   46661632u
#define O_X5MAX  46792704u
#define O_BIAS   46796800u
#define O_Y1     46797824u
#define O_Y2     55186432u
#define O_Y3     63575040u
#define O_SD     67769344u    // 4*8192*4*10 = 1310720 floats
#define O_SI     69080064u    // 1310720 ints
#define SCRATCH_FLOATS 70390784u

__device__ __align__(16) float g_scratch[SCRATCH_FLOATS];

// ---------------- f32x2 packed helpers (sm_103a) ----------------
__device__ __forceinline__ void unpack2(unsigned long long v, float& lo, float& hi) {
    asm("mov.b64 {%0, %1}, %2;" : "=f"(lo), "=f"(hi) : "l"(v));
}
__device__ __forceinline__ unsigned long long fma2(unsigned long long a,
                                                   unsigned long long b,
                                                   unsigned long long c) {
    unsigned long long d;
    asm("fma.rn.f32x2 %0, %1, %2, %3;" : "=l"(d) : "l"(a), "l"(b), "l"(c));
    return d;
}

// ---------------- build x0 = concat(targets, targets) ----------------
__global__ void build_x0_kernel(const float* __restrict__ t, float* __restrict__ x0) {
    int i = blockIdx.x * blockDim.x + threadIdx.x;
    if (i < BATCH * NPTS * 6) {
        int pt = i / 6, c = i % 6;
        x0[i] = t[pt * 3 + (c < 3 ? c : c - 3)];
    }
}

// ---------------- small-C KNN (C=6), thread per query (R2-proven) ----------------
template<int C>
__global__ void knn_kernel(const float* __restrict__ x, int* __restrict__ idxout) {
    __shared__ float tile[128 * C];
    __shared__ float tnorm[128];
    const int b = blockIdx.y;
    const int q = blockIdx.x * 128 + threadIdx.x;
    const float* xb = x + (size_t)b * NPTS * C;

    float qf[C];
    float qn = 0.f;
    #pragma unroll
    for (int c = 0; c < C; c++) { qf[c] = xb[q * C + c]; qn = fmaf(qf[c], qf[c], qn); }

    float bd[KNNK]; int bi[KNNK];
    #pragma unroll
    for (int i = 0; i < KNNK; i++) { bd[i] = CUDART_INF_F; bi[i] = 0; }

    for (int t0 = 0; t0 < NPTS; t0 += 128) {
        __syncthreads();
        for (int i = threadIdx.x; i < 128 * C; i += 128) tile[i] = xb[t0 * C + i];
        __syncthreads();
        {
            float s = 0.f;
            #pragma unroll
            for (int c = 0; c < C; c++) {
                float v = tile[threadIdx.x * C + c];
                s = fmaf(v, v, s);
            }
            tnorm[threadIdx.x] = s;
        }
        __syncthreads();
        for (int j = 0; j < 128; j++) {
            float d0 = 0.f, d1 = 0.f;
            #pragma unroll
            for (int c = 0; c < C; c += 2) {
                d0 = fmaf(qf[c + 0], tile[j * C + c + 0], d0);
                d1 = fmaf(qf[c + 1], tile[j * C + c + 1], d1);
            }
            float d = qn + tnorm[j] - 2.f * (d0 + d1);
            if (d < bd[KNNK - 1]) {
                bd[KNNK - 1] = d; bi[KNNK - 1] = t0 + j;
                #pragma unroll
                for (int s = KNNK - 1; s > 0; s--) {
                    if (bd[s] < bd[s - 1]) {
                        float td = bd[s]; bd[s] = bd[s - 1]; bd[s - 1] = td;
                        int   ti = bi[s]; bi[s] = bi[s - 1]; bi[s - 1] = ti;
                    }
                }
            }
        }
    }
    int* o = idxout + ((size_t)b * NPTS + q) * KNNK;
    #pragma unroll
    for (int i = 0; i < KNNK; i++) o[i] = bi[i];
}

// ---------------- KNN C=64: candidate-split + packed f32x2 dot (R4-proven) ----------------
template<int C>
__global__ __launch_bounds__(128)
void knn_split_kernel(const float* __restrict__ x,
                      float* __restrict__ sd, int* __restrict__ si) {
    __shared__ float tile[128 * C];
    __shared__ float tnorm[128];
    const int b = blockIdx.z;
    const int sp = blockIdx.y;
    const int q = blockIdx.x * 128 + threadIdx.x;
    const float* xb = x + (size_t)b * NPTS * C;
    const int cand0 = sp * SPLITLEN;

    unsigned long long qp[C / 2];
    {
        const ulonglong2* qr = (const ulonglong2*)(xb + (size_t)q * C);
        #pragma unroll
        for (int i = 0; i < C / 4; i++) {
            ulonglong2 v = qr[i];
            qp[2 * i] = v.x; qp[2 * i + 1] = v.y;
        }
    }

    float bd[KNNK]; int bi[KNNK];
    #pragma unroll
    for (int i = 0; i < KNNK; i++) { bd[i] = CUDART_INF_F; bi[i] = 0; }

    for (int t0 = cand0; t0 < cand0 + SPLITLEN; t0 += 128) {
        __syncthreads();
        {
            const float4* src = (const float4*)(xb + (size_t)t0 * C);
            float4* dst = (float4*)tile;
            for (int i = threadIdx.x; i < 128 * (C / 4); i += 128) dst[i] = src[i];
        }
        __syncthreads();
        {
            const unsigned long long* tr =
                (const unsigned long long*)(tile + threadIdx.x * C);
            unsigned long long a0 = 0ull, a1 = 0ull;
            #pragma unroll
            for (int i = 0; i < C / 2; i += 2) {
                a0 = fma2(tr[i], tr[i], a0);
                a1 = fma2(tr[i + 1], tr[i + 1], a1);
            }
            float l0, h0, l1, h1;
            unpack2(a0, l0, h0); unpack2(a1, l1, h1);
            tnorm[threadIdx.x] = (l0 + h0) + (l1 + h1);
        }
        __syncthreads();
        for (int j = 0; j < 128; j++) {
            const unsigned long long* tr = (const unsigned long long*)(tile + j * C);
            unsigned long long a0 = 0ull, a1 = 0ull, a2 = 0ull, a3 = 0ull;
            #pragma unroll
            for (int i = 0; i < C / 2; i += 4) {
                a0 = fma2(qp[i + 0], tr[i + 0], a0);
                a1 = fma2(qp[i + 1], tr[i + 1], a1);
                a2 = fma2(qp[i + 2], tr[i + 2], a2);
                a3 = fma2(qp[i + 3], tr[i + 3], a3);
            }
            float l0, h0, l1, h1, l2, h2, l3, h3;
            unpack2(a0, l0, h0); unpack2(a1, l1, h1);
            unpack2(a2, l2, h2); unpack2(a3, l3, h3);
            float dot = ((l0 + h0) + (l1 + h1)) + ((l2 + h2) + (l3 + h3));
            float d = fmaf(-2.f, dot, tnorm[j]);
            if (d < bd[KNNK - 1]) {
                bd[KNNK - 1] = d; bi[KNNK - 1] = t0 + j;
                #pragma unroll
                for (int s = KNNK - 1; s > 0; s--) {
                    if (bd[s] < bd[s - 1]) {
                        float td = bd[s]; bd[s] = bd[s - 1]; bd[s - 1] = td;
                        int   ti = bi[s]; bi[s] = bi[s - 1]; bi[s - 1] = ti;
                    }
                }
            }
        }
    }
    size_t o = (((size_t)b * NPTS + q) * NSPLIT + sp) * KNNK;
    #pragma unroll
    for (int i = 0; i < KNNK; i++) { sd[o + i] = bd[i]; si[o + i] = bi[i]; }
}

// merge NSPLIT partial top-10 lists into final indices
__global__ void knn_merge_kernel(const float* __restrict__ sd, const int* __restrict__ si,
                                 int* __restrict__ idxout) {
    int p = blockIdx.x * 256 + threadIdx.x;
    if (p >= BATCH * NPTS) return;
    const float* d = sd + (size_t)p * NSPLIT * KNNK;
    const int* ix = si + (size_t)p * NSPLIT * KNNK;
    float bd[KNNK]; int bi[KNNK];
    #pragma unroll
    for (int i = 0; i < KNNK; i++) { bd[i] = CUDART_INF_F; bi[i] = 0; }
    #pragma unroll 4
    for (int s = 0; s < NSPLIT * KNNK; s++) {
        float dv = d[s];
        if (dv < bd[KNNK - 1]) {
            bd[KNNK - 1] = dv; bi[KNNK - 1] = ix[s];
            #pragma unroll
            for (int t = KNNK - 1; t > 0; t--) {
                if (bd[t] < bd[t - 1]) {
                    float td = bd[t]; bd[t] = bd[t - 1]; bd[t - 1] = td;
                    int   ti = bi[t]; bi[t] = bi[t - 1]; bi[t - 1] = ti;
                }
            }
        }
    }
    int* o = idxout + (size_t)p * KNNK;
    #pragma unroll
    for (int i = 0; i < KNNK; i++) o[i] = bi[i];
}

// ---------------- edge conv: center-hoisted + dup-packed f32x2 ----------------
// f @ w1 = (nb-xr)@w1[:C] + xr@w1[C:] ; second term neighbor-invariant.
// Features stored duplicated ((v,v) pairs) in shared so the inner loop is
// LDS.64(feat-dup, broadcast) + LDS.64(weight ch-pair, conflict-free) + FMA2.
// block 512 = 16 warps, one point per warp, 2 output channels per lane.
template<int C, bool TWO>
__global__ void edge_conv_kernel(const float* __restrict__ x, const int* __restrict__ knn,
                                 const float* __restrict__ w1, const float* __restrict__ w2,
                                 const float* __restrict__ pa, int ai1, int ai2,
                                 float* __restrict__ out) {
    constexpr int F = 2 * C;
    constexpr int PPB = 16;
    constexpr int WSLOT = 4 * C + (TWO ? 128 : 0);   // cdup + ddup (+ hdup)
    extern __shared__ float sm[];
    float* ws1 = sm;                                  // [F][64]
    float* ws2 = ws1 + F * 64;                        // [64][64] if TWO
    float* wsl = ws2 + (TWO ? 4096 : 0);              // per-warp slots

    int tid = threadIdx.x;
    for (int i = tid; i < F * 64; i += 512) ws1[i] = w1[i];
    if (TWO) for (int i = tid; i < 4096; i += 512) ws2[i] = w2[i];
    float a1 = pa[ai1];
    float a2 = TWO ? pa[ai2] : 0.f;
    __syncthreads();

    int g = tid >> 5, lt = tid & 31;
    size_t pt = (size_t)blockIdx.x * PPB + g;
    int b = (int)(pt / NPTS);
    int n = (int)(pt % NPTS);
    const float* xb = x + (size_t)b * NPTS * C;
    const int* nbr = knn + pt * KNNK;
    float* cdup = wsl + g * WSLOT;        // [2C] dup'd center
    float* ddup = cdup + 2 * C;           // [2C] dup'd diff
    float* hdup = ddup + 2 * C;           // [128] dup'd h1 (TWO)

    // center features, duplicated
    for (int c = lt; c < C; c += 32) {
        float v = xb[(size_t)n * C + c];
        *(float2*)(cdup + 2 * c) = make_float2(v, v);
    }
    __syncwarp();

    // neighbor-invariant contribution: xr @ w1[C:]
    unsigned long long cc = 0ull;
    #pragma unroll 8
    for (int c = 0; c < C; c++) {
        unsigned long long fd = *(const unsigned long long*)(cdup + 2 * c);
        unsigned long long wp = *(const unsigned long long*)(ws1 + (size_t)(C + c) * 64 + 2 * lt);
        cc = fma2(fd, wp, cc);
    }

    float mx0 = -CUDART_INF_F, mx1 = -CUDART_INF_F;
    for (int j = 0; j < KNNK; j++) {
        int nb = nbr[j];
        __syncwarp();
        for (int c = lt; c < C; c += 32) {
            float v = xb[(size_t)nb * C + c] - cdup[2 * c];
            *(float2*)(ddup + 2 * c) = make_float2(v, v);
        }
        __syncwarp();
        unsigned long long acc = cc;
        #pragma unroll 8
        for (int c = 0; c < C; c++) {
            unsigned long long fd = *(const unsigned long long*)(ddup + 2 * c);
            unsigned long long wp = *(const unsigned long long*)(ws1 + (size_t)c * 64 + 2 * lt);
            acc = fma2(fd, wp, acc);
        }
        float s0, s1;
        unpack2(acc, s0, s1);
        float h0  = s0 >= 0.f ? s0 : a1 * s0;
        float hh1 = s1 >= 0.f ? s1 : a1 * s1;
        if (TWO) {
            *(float2*)(hdup + 4 * lt)     = make_float2(h0, h0);
            *(float2*)(hdup + 4 * lt + 2) = make_float2(hh1, hh1);
            __syncwarp();
            unsigned long long acc2 = 0ull;
            #pragma unroll 8
            for (int c = 0; c < 64; c++) {
                unsigned long long fd = *(const unsigned long long*)(hdup + 2 * c);
                unsigned long long wp = *(const unsigned long long*)(ws2 + (size_t)c * 64 + 2 * lt);
                acc2 = fma2(fd, wp, acc2);
            }
            float t0, t1;
            unpack2(acc2, t0, t1);
            h0  = t0 >= 0.f ? t0 : a2 * t0;
            hh1 = t1 >= 0.f ? t1 : a2 * t1;
        }
        mx0 = fmaxf(mx0, h0);
        mx1 = fmaxf(mx1, hh1);
    }
    *(float2*)(out + pt * 64 + 2 * lt) = make_float2(mx0, mx1);
}

// ---------------- concat x4 = [x1|x2|x3] ----------------
__global__ void concat_x4_kernel(const float* __restrict__ x1, const float* __restrict__ x2,
                                 const float* __restrict__ x3, float* __restrict__ x4) {
    int i = blockIdx.x * 256 + threadIdx.x;
    if (i < BATCH * NPTS * 192) {
        int pt = i / 192, c = i % 192;
        float v = (c < 64) ? x1[pt * 64 + c]
                : (c < 128) ? x2[pt * 64 + c - 64]
                : x3[pt * 64 + c - 128];
        x4[i] = v;
    }
}

// ---------------- SGEMM + per-batch bias + PReLU epilogue (R2-proven) ----------------
__global__ void gemm_prelu_kernel(const float* __restrict__ A, const float* __restrict__ B,
                                  float* __restrict__ C, const float* __restrict__ bias,
                                  const float* __restrict__ pa, int aidx,
                                  int K, int Nc) {
    __shared__ float As[16][64];
    __shared__ float Bs[16][64];
    int tid = threadIdx.x;
    int tx = tid & 15, ty = tid >> 4;
    int m0 = blockIdx.x * 64, n0 = blockIdx.y * 64;

    float acc[8][4];
    #pragma unroll
    for (int r = 0; r < 8; r++)
        #pragma unroll
        for (int c = 0; c < 4; c++) acc[r][c] = 0.f;

    for (int k0 = 0; k0 < K; k0 += 16) {
        #pragma unroll
        for (int l = 0; l < 2; l++) {
            int i = tid * 2 + l;
            int m = i >> 2, kc = (i & 3) * 4;
            float4 v = *(const float4*)(A + (size_t)(m0 + m) * K + k0 + kc);
            As[kc + 0][m] = v.x; As[kc + 1][m] = v.y;
            As[kc + 2][m] = v.z; As[kc + 3][m] = v.w;
            int kb = i >> 4, nb = (i & 15) * 4;
            float4 w = *(const float4*)(B + (size_t)(k0 + kb) * Nc + n0 + nb);
            *(float4*)(&Bs[kb][nb]) = w;
        }
        __syncthreads();
        #pragma unroll
        for (int kk = 0; kk < 16; kk++) {
            float a[8], bb[4];
            #pragma unroll
            for (int r = 0; r < 8; r++) a[r] = As[kk][ty * 8 + r];
            #pragma unroll
            for (int c = 0; c < 4; c++) bb[c] = Bs[kk][tx * 4 + c];
            #pragma unroll
            for (int r = 0; r < 8; r++)
                #pragma unroll
                for (int c = 0; c < 4; c++)
                    acc[r][c] = fmaf(a[r], bb[c], acc[r][c]);
        }
        __syncthreads();
    }

    float al = pa[aidx];
    #pragma unroll
    for (int r = 0; r < 8; r++) {
        size_t m = (size_t)m0 + ty * 8 + r;
        int n = n0 + tx * 4;
        float4 v;
        float bv0 = 0.f, bv1 = 0.f, bv2 = 0.f, bv3 = 0.f;
        if (bias) {
            const float* brow = bias + (m >> 13) * Nc;
            bv0 = brow[n]; bv1 = brow[n + 1]; bv2 = brow[n + 2]; bv3 = brow[n + 3];
        }
        float e0 = acc[r][0] + bv0, e1 = acc[r][1] + bv1;
        float e2 = acc[r][2] + bv2, e3 = acc[r][3] + bv3;
        v.x = e0 >= 0.f ? e0 : al * e0;
        v.y = e1 >= 0.f ? e1 : al * e1;
        v.z = e2 >= 0.f ? e2 : al * e2;
        v.w = e3 >= 0.f ? e3 : al * e3;
        *(float4*)(C + m * Nc + n) = v;
    }
}

// ---------------- global max over N + bias from w7 tail ----------------
__global__ void max1_kernel(const float* __restrict__ x5, float* __restrict__ pmax) {
    int b = blockIdx.y, chunk = blockIdx.x, c = threadIdx.x;
    const float* p = x5 + ((size_t)b * NPTS + (size_t)chunk * 256) * 1024 + c;
    float m = -CUDART_INF_F;
    for (int n = 0; n < 256; n++) m = fmaxf(m, p[(size_t)n * 1024]);
    pmax[((size_t)b * 32 + chunk) * 1024 + c] = m;
}
__global__ void max2_kernel(const float* __restrict__ pmax, float* __restrict__ x5max) {
    int b = blockIdx.x, c = threadIdx.x;
    float m = -CUDART_INF_F;
    for (int k = 0; k < 32; k++) m = fmaxf(m, pmax[((size_t)b * 32 + k) * 1024 + c]);
    x5max[b * 1024 + c] = m;
}
__global__ void bias_kernel(const float* __restrict__ x5max, const float* __restrict__ w7,
                            float* __restrict__ bias) {
    int b = blockIdx.x, j = threadIdx.x;
    float s = 0.f;
    for (int c = 0; c < 1024; c++)
        s = fmaf(x5max[b * 1024 + c], w7[(size_t)(192 + c) * 256 + j], s);
    bias[b * 256 + j] = s;
}

// ---------------- final 128->2 layer ----------------
__global__ void final_kernel(const float* __restrict__ y3, const float* __restrict__ w10,
                             const float* __restrict__ pa, float* __restrict__ out) {
    __shared__ float ws[256];
    int tid = threadIdx.x;
    ws[tid * 2] = w10[tid * 2];
    ws[tid * 2 + 1] = w10[tid * 2 + 1];
    __syncthreads();
    int warp = tid >> 5, lane = tid & 31;
    size_t pt = (size_t)blockIdx.x * 4 + warp;
    const float* row = y3 + pt * 128;
    float s0 = 0.f, s1 = 0.f;
    for (int c = lane; c < 128; c += 32) {
        float v = row[c];
        s0 = fmaf(v, ws[c * 2], s0);
        s1 = fmaf(v, ws[c * 2 + 1], s1);
    }
    #pragma unroll
    for (int o = 16; o > 0; o >>= 1) {
        s0 += __shfl_down_sync(0xffffffffu, s0, o);
        s1 += __shfl_down_sync(0xffffffffu, s1, o);
    }
    if (lane == 0) {
        float a = pa[9];
        out[pt * 2]     = s0 >= 0.f ? s0 : a * s0;
        out[pt * 2 + 1] = s1 >= 0.f ? s1 : a * s1;
    }
}

// ---------------- host orchestration ----------------
extern "C" void kernel_launch(void* const* d_in, const int* in_sizes, int n_in,
                              void* d_out, int out_size) {
    const float* targets = (const float*)d_in[0];
    const float* w[10];
    for (int i = 0; i < 10; i++) w[i] = (const float*)d_in[1 + i];
    const float* pa = (const float*)d_in[11];
    float* out = (float*)d_out;

    float* base = nullptr;
    cudaGetSymbolAddress((void**)&base, g_scratch);
    float* x0    = base + O_X0;
    int*   idx   = (int*)(base + O_IDX);
    float* x1    = base + O_X1;
    float* x2    = base + O_X2;
    float* x3    = base + O_X3;
    float* x4    = base + O_X4;
    float* x5    = base + O_X5;
    float* pmax  = base + O_PMAX;
    float* x5max = base + O_X5MAX;
    float* bias  = base + O_BIAS;
    float* y1    = base + O_Y1;
    float* y2    = base + O_Y2;
    float* y3    = base + O_Y3;
    float* sd    = base + O_SD;
    int*   si    = (int*)(base + O_SI);

    // edge conv smem: ws1(F*64) [+ ws2 4096] + 16*WSLOT
    const int smem6t  = (12 * 64 + 4096 + 16 * (4 * 6 + 128)) * 4;    // 28.2KB
    const int smem64t = (128 * 64 + 4096 + 16 * (4 * 64 + 128)) * 4;  // 73.7KB
    const int smem64f = (128 * 64 + 16 * (4 * 64)) * 4;               // 49.2KB

    cudaFuncSetAttribute(edge_conv_kernel<64, true>,
                         cudaFuncAttributeMaxDynamicSharedMemorySize, smem64t);
    cudaFuncSetAttribute(edge_conv_kernel<64, false>,
                         cudaFuncAttributeMaxDynamicSharedMemorySize, smem64f);

    build_x0_kernel<<<(BATCH * NPTS * 6 + 255) / 256, 256>>>(targets, x0);

    knn_kernel<6><<<dim3(NPTS / 128, BATCH), 128>>>(x0, idx);
    edge_conv_kernel<6, true><<<BATCH * NPTS / 16, 512, smem6t>>>(x0, idx, w[0], w[1], pa, 0, 1, x1);

    knn_split_kernel<64><<<dim3(NPTS / 128, NSPLIT, BATCH), 128>>>(x1, sd, si);
    knn_merge_kernel<<<(BATCH * NPTS + 255) / 256, 256>>>(sd, si, idx);
    edge_conv_kernel<64, true><<<BATCH * NPTS / 16, 512, smem64t>>>(x1, idx, w[2], w[3], pa, 2, 3, x2);

    knn_split_kernel<64><<<dim3(NPTS / 128, NSPLIT, BATCH), 128>>>(x2, sd, si);
    knn_merge_kernel<<<(BATCH * NPTS + 255) / 256, 256>>>(sd, si, idx);
    edge_conv_kernel<64, false><<<BATCH * NPTS / 16, 512, smem64f>>>(x2, idx, w[4], nullptr, pa, 4, 4, x3);

    concat_x4_kernel<<<(BATCH * NPTS * 192 + 255) / 256, 256>>>(x1, x2, x3, x4);

    gemm_prelu_kernel<<<dim3(BATCH * NPTS / 64, 1024 / 64), 128>>>(x4, w[5], x5, nullptr, pa, 5, 192, 1024);
    max1_kernel<<<dim3(32, BATCH), 1024>>>(x5, pmax);
    max2_kernel<<<BATCH, 1024>>>(pmax, x5max);
    bias_kernel<<<BATCH, 256>>>(x5max, w[6], bias);

    gemm_prelu_kernel<<<dim3(BATCH * NPTS / 64, 256 / 64), 128>>>(x4, w[6], y1, bias, pa, 6, 192, 256);
    gemm_prelu_kernel<<<dim3(BATCH * NPTS / 64, 256 / 64), 128>>>(y1, w[7], y2, nullptr, pa, 7, 256, 256);
    gemm_prelu_kernel<<<dim3(BATCH * NPTS / 64, 128 / 64), 128>>>(y2, w[8], y3, nullptr, pa, 8, 256, 128);
    final_kernel<<<BATCH * NPTS / 4, 128>>>(y3, w[9], pa, out);

    (void)in_sizes; (void)n_in; (void)out_size;
}